// round 5
// baseline (speedup 1.0000x reference)
#include <cuda_runtime.h>

// Problem constants (fixed shapes per reference)
#define BATCH 16
#define N1    1024
#define NP    4096
#define D1    256
#define D2    128
#define DIN   384          // D1 + D2
#define HID   256
#define MTOT  (BATCH * NP) // 65536
#define F32_EPS 1.1920929e-07f
#define BN_EPS  1e-5f

// Scratch (static device globals: allocation-free)
__device__ float g_x[MTOT * DIN];     // concat(interp, features2)  [65536, 384]
__device__ float g_y[MTOT * HID];     // layer-1 pre-BN output      [65536, 256]
__device__ float g_stats[4 * HID];    // [sum1, sumsq1, sum2, sumsq2]
__device__ float g_bn[4 * HID];       // [a1, s1, a2, s2]  (y*a + s form)

// ---------------------------------------------------------------------------
__global__ void zero_stats_kernel() {
    g_stats[threadIdx.x] = 0.0f;
}

// ---------------------------------------------------------------------------
// 3-NN inverse-distance interpolation + concat. One warp per query (4 queries
// per warp sequentially), xyz1 for the batch staged in shared memory.
__global__ __launch_bounds__(256) void interp_kernel(
    const float* __restrict__ xyz1, const float* __restrict__ xyz2,
    const float* __restrict__ f1,   const float* __restrict__ f2)
{
    __shared__ float sx[N1 * 3];
    const int b = blockIdx.y;
    const float* x1b = xyz1 + (size_t)b * N1 * 3;
    for (int i = threadIdx.x; i < N1 * 3; i += blockDim.x) sx[i] = x1b[i];
    __syncthreads();

    const int warp = threadIdx.x >> 5, lane = threadIdx.x & 31;
    const int qbase = blockIdx.x * 32 + warp * 4;
    const float* f1b = f1 + (size_t)b * N1 * D1;

    for (int q = 0; q < 4; ++q) {
        const int j = qbase + q;
        const float* qp = xyz2 + ((size_t)b * NP + j) * 3;
        const float qx = qp[0], qy = qp[1], qz = qp[2];

        // per-lane 3 smallest distances (ascending), tie -> smaller index
        float d0 = 3.4e38f, d1 = 3.4e38f, d2 = 3.4e38f;
        int   i0 = 0x7fffffff, i1 = 0x7fffffff, i2 = 0x7fffffff;
        for (int i = lane; i < N1; i += 32) {
            const float dx = qx - sx[3*i];
            const float dy = qy - sx[3*i+1];
            const float dz = qz - sx[3*i+2];
            const float d  = fmaf(dx, dx, fmaf(dy, dy, dz * dz));
            if (d < d2) {
                if (d < d1) {
                    d2 = d1; i2 = i1;
                    if (d < d0) { d1 = d0; i1 = i0; d0 = d; i0 = i; }
                    else        { d1 = d;  i1 = i; }
                } else { d2 = d; i2 = i; }
            }
        }
        // butterfly merge of sorted-3 lists (symmetric tie-break on index)
        for (int off = 16; off; off >>= 1) {
            float e0 = __shfl_xor_sync(0xffffffffu, d0, off);
            float e1 = __shfl_xor_sync(0xffffffffu, d1, off);
            float e2 = __shfl_xor_sync(0xffffffffu, d2, off);
            int   j0 = __shfl_xor_sync(0xffffffffu, i0, off);
            int   j1 = __shfl_xor_sync(0xffffffffu, i1, off);
            int   j2 = __shfl_xor_sync(0xffffffffu, i2, off);
            float r0, r1, r2; int s0, s1, s2;
            #pragma unroll
            for (int t = 0; t < 3; ++t) {
                const bool takeA = (d0 < e0) || (d0 == e0 && i0 < j0);
                float rv; int ri;
                if (takeA) { rv = d0; ri = i0; d0 = d1; i0 = i1; d1 = d2; i1 = i2; d2 = 3.4e38f; i2 = 0x7fffffff; }
                else       { rv = e0; ri = j0; e0 = e1; j0 = j1; e1 = e2; j1 = j2; e2 = 3.4e38f; j2 = 0x7fffffff; }
                if (t == 0) { r0 = rv; s0 = ri; }
                else if (t == 1) { r1 = rv; s1 = ri; }
                else { r2 = rv; s2 = ri; }
            }
            d0 = r0; d1 = r1; d2 = r2; i0 = s0; i1 = s1; i2 = s2;
        }

        float w0 = 1.0f / (d0 + F32_EPS);
        float w1 = 1.0f / (d1 + F32_EPS);
        float w2 = 1.0f / (d2 + F32_EPS);
        const float inv_sum = 1.0f / (w0 + w1 + w2);
        w0 *= inv_sum; w1 *= inv_sum; w2 *= inv_sum;

        const float4* r0p = (const float4*)(f1b + (size_t)i0 * D1);
        const float4* r1p = (const float4*)(f1b + (size_t)i1 * D1);
        const float4* r2p = (const float4*)(f1b + (size_t)i2 * D1);
        float* xo = g_x + ((size_t)b * NP + j) * DIN;
        for (int c = lane; c < D1 / 4; c += 32) {
            const float4 a = r0p[c], bb = r1p[c], cc = r2p[c];
            float4 o;
            o.x = w0*a.x + w1*bb.x + w2*cc.x;
            o.y = w0*a.y + w1*bb.y + w2*cc.y;
            o.z = w0*a.z + w1*bb.z + w2*cc.z;
            o.w = w0*a.w + w1*bb.w + w2*cc.w;
            ((float4*)xo)[c] = o;
        }
        const float4* ff2 = (const float4*)(f2 + ((size_t)b * NP + j) * D2);
        float4* xo2 = (float4*)(xo + D1);
        for (int c = lane; c < D2 / 4; c += 32) xo2[c] = ff2[c];
    }
}

// ---------------------------------------------------------------------------
// fp32 tiled GEMM: out[m][n] = sum_k A[m][k] * W[n][k] + bias[n]
// BM=128, BN=64, BK=16, 256 threads, 8x4 per thread.
// LAYER==1 applies relu(a1[k]*A + s1[k]) on A-tile load (fused BN+ReLU of
// layer 1). Epilogue accumulates per-channel sum/sumsq into g_stats.
template<int K, int LAYER>
__global__ __launch_bounds__(256) void gemm_kernel(
    const float* __restrict__ W, const float* __restrict__ bias,
    float* __restrict__ out_ext)
{
    __shared__ float As[16][128 + 4];
    __shared__ float Bs[16][64 + 4];
    __shared__ float csum[64], csq[64];

    const float* A   = (LAYER == 0) ? g_x : g_y;
    float*       outp = (LAYER == 0) ? g_y : out_ext;
    const int SOFF = LAYER * 2 * HID;

    const int tid = threadIdx.x;
    const int tx = tid & 15, ty = tid >> 4;
    const int m0 = blockIdx.x * 128;
    const int n0 = blockIdx.y * 64;

    float acc[8][4];
    #pragma unroll
    for (int i = 0; i < 8; ++i)
        #pragma unroll
        for (int jj = 0; jj < 4; ++jj) acc[i][jj] = 0.0f;

    for (int k0 = 0; k0 < K; k0 += 16) {
        // A tile: 128 rows x 16 k
        #pragma unroll
        for (int r = 0; r < 2; ++r) {
            const int idx = tid + r * 256;
            const int row = idx >> 2;
            const int c4  = (idx & 3) * 4;
            float4 v = *(const float4*)(A + (size_t)(m0 + row) * K + k0 + c4);
            if (LAYER == 1) {
                const float4 aa = *(const float4*)&g_bn[k0 + c4];
                const float4 ss = *(const float4*)&g_bn[HID + k0 + c4];
                v.x = fmaxf(fmaf(v.x, aa.x, ss.x), 0.0f);
                v.y = fmaxf(fmaf(v.y, aa.y, ss.y), 0.0f);
                v.z = fmaxf(fmaf(v.z, aa.z, ss.z), 0.0f);
                v.w = fmaxf(fmaf(v.w, aa.w, ss.w), 0.0f);
            }
            As[c4    ][row] = v.x;
            As[c4 + 1][row] = v.y;
            As[c4 + 2][row] = v.z;
            As[c4 + 3][row] = v.w;
        }
        // B tile: 64 n-rows x 16 k
        {
            const int row = tid >> 2;
            const int c4  = (tid & 3) * 4;
            const float4 v = *(const float4*)(W + (size_t)(n0 + row) * K + k0 + c4);
            Bs[c4    ][row] = v.x;
            Bs[c4 + 1][row] = v.y;
            Bs[c4 + 2][row] = v.z;
            Bs[c4 + 3][row] = v.w;
        }
        __syncthreads();

        #pragma unroll
        for (int kk = 0; kk < 16; ++kk) {
            const float4 a0 = *(const float4*)&As[kk][ty * 8];
            const float4 a1 = *(const float4*)&As[kk][ty * 8 + 4];
            const float4 bb = *(const float4*)&Bs[kk][tx * 4];
            const float av[8] = {a0.x, a0.y, a0.z, a0.w, a1.x, a1.y, a1.z, a1.w};
            const float bv[4] = {bb.x, bb.y, bb.z, bb.w};
            #pragma unroll
            for (int i = 0; i < 8; ++i)
                #pragma unroll
                for (int jj = 0; jj < 4; ++jj)
                    acc[i][jj] = fmaf(av[i], bv[jj], acc[i][jj]);
        }
        __syncthreads();
    }

    // Epilogue: bias, store, per-channel stats
    if (tid < 64) { csum[tid] = 0.0f; csq[tid] = 0.0f; }
    __syncthreads();

    const float4 bia = *(const float4*)(bias + n0 + tx * 4);
    float psum[4] = {0, 0, 0, 0}, psq[4] = {0, 0, 0, 0};
    #pragma unroll
    for (int i = 0; i < 8; ++i) {
        float4 v;
        v.x = acc[i][0] + bia.x;
        v.y = acc[i][1] + bia.y;
        v.z = acc[i][2] + bia.z;
        v.w = acc[i][3] + bia.w;
        *(float4*)(outp + (size_t)(m0 + ty * 8 + i) * HID + n0 + tx * 4) = v;
        psum[0] += v.x; psq[0] += v.x * v.x;
        psum[1] += v.y; psq[1] += v.y * v.y;
        psum[2] += v.z; psq[2] += v.z * v.z;
        psum[3] += v.w; psq[3] += v.w * v.w;
    }
    #pragma unroll
    for (int jj = 0; jj < 4; ++jj) {
        atomicAdd(&csum[tx * 4 + jj], psum[jj]);
        atomicAdd(&csq[tx * 4 + jj],  psq[jj]);
    }
    __syncthreads();
    if (tid < 64) {
        atomicAdd(&g_stats[SOFF + n0 + tid],        csum[tid]);
        atomicAdd(&g_stats[SOFF + HID + n0 + tid],  csq[tid]);
    }
}

// ---------------------------------------------------------------------------
__global__ void bn_finalize_kernel(const float* __restrict__ g,
                                   const float* __restrict__ beta, int layer)
{
    const int c = threadIdx.x;
    const float invM = 1.0f / (float)MTOT;
    const float sum = g_stats[layer * 2 * HID + c];
    const float sq  = g_stats[layer * 2 * HID + HID + c];
    const float mu  = sum * invM;
    const float var = sq * invM - mu * mu;
    const float a   = rsqrtf(var + BN_EPS) * g[c];
    g_bn[layer * 2 * HID + c]       = a;
    g_bn[layer * 2 * HID + HID + c] = beta[c] - mu * a;
}

// ---------------------------------------------------------------------------
__global__ __launch_bounds__(256) void final_norm_kernel(float* __restrict__ out)
{
    const int i = blockIdx.x * 256 + threadIdx.x;   // float4 index
    float4 v = ((float4*)out)[i];
    const int c = (i * 4) & (HID - 1);
    const float4 a = *(const float4*)&g_bn[2 * HID + c];
    const float4 s = *(const float4*)&g_bn[3 * HID + c];
    v.x = fmaxf(fmaf(v.x, a.x, s.x), 0.0f);
    v.y = fmaxf(fmaf(v.y, a.y, s.y), 0.0f);
    v.z = fmaxf(fmaf(v.z, a.z, s.z), 0.0f);
    v.w = fmaxf(fmaf(v.w, a.w, s.w), 0.0f);
    ((float4*)out)[i] = v;
}

// ---------------------------------------------------------------------------
extern "C" void kernel_launch(void* const* d_in, const int* in_sizes, int n_in,
                              void* d_out, int out_size)
{
    const float* xyz1  = (const float*)d_in[0];
    const float* xyz2  = (const float*)d_in[1];
    const float* f1    = (const float*)d_in[2];
    const float* f2    = (const float*)d_in[3];
    const float* W1    = (const float*)d_in[4];
    const float* b1    = (const float*)d_in[5];
    const float* g1    = (const float*)d_in[6];
    const float* beta1 = (const float*)d_in[7];
    const float* W2    = (const float*)d_in[8];
    const float* b2    = (const float*)d_in[9];
    const float* g2    = (const float*)d_in[10];
    const float* beta2 = (const float*)d_in[11];
    float* out = (float*)d_out;

    zero_stats_kernel<<<1, 1024>>>();
    interp_kernel<<<dim3(NP / 32, BATCH), 256>>>(xyz1, xyz2, f1, f2);
    gemm_kernel<DIN, 0><<<dim3(MTOT / 128, HID / 64), 256>>>(W1, b1, nullptr);
    bn_finalize_kernel<<<1, HID>>>(g1, beta1, 0);
    gemm_kernel<HID, 1><<<dim3(MTOT / 128, HID / 64), 256>>>(W2, b2, out);
    bn_finalize_kernel<<<1, HID>>>(g2, beta2, 1);
    final_norm_kernel<<<(MTOT * HID / 4) / 256, 256>>>(out);
}

// round 6
// speedup vs baseline: 1.1571x; 1.1571x over previous
#include <cuda_runtime.h>
#include <cuda_bf16.h>

// Problem constants (fixed shapes per reference)
#define BATCH 16
#define N1    1024
#define NP    4096
#define D1    256
#define D2    128
#define DIN   384          // D1 + D2
#define HID   256
#define MTOT  (BATCH * NP) // 65536
#define F32_EPS 1.1920929e-07f
#define BN_EPS  1e-5f

// Scratch (static device globals: allocation-free)
__device__ float g_x[MTOT * DIN];     // concat(interp, features2)  [65536, 384]
__device__ float g_y[MTOT * HID];     // layer-1 pre-BN output      [65536, 256]
__device__ float g_stats[4 * HID];    // [sum1, sumsq1, sum2, sumsq2]
__device__ float g_bn[4 * HID];       // [a1, s1, a2, s2]  (y*a + s form)

// ---------------------------------------------------------------------------
__global__ void zero_stats_kernel() {
    g_stats[threadIdx.x] = 0.0f;
}

// ---------------------------------------------------------------------------
// 3-NN inverse-distance interpolation + concat. One warp per query (4 queries
// per warp sequentially), xyz1 for the batch staged in shared memory.
__global__ __launch_bounds__(256) void interp_kernel(
    const float* __restrict__ xyz1, const float* __restrict__ xyz2,
    const float* __restrict__ f1,   const float* __restrict__ f2)
{
    __shared__ float sx[N1 * 3];
    const int b = blockIdx.y;
    const float* x1b = xyz1 + (size_t)b * N1 * 3;
    for (int i = threadIdx.x; i < N1 * 3; i += blockDim.x) sx[i] = x1b[i];
    __syncthreads();

    const int warp = threadIdx.x >> 5, lane = threadIdx.x & 31;
    const int qbase = blockIdx.x * 32 + warp * 4;
    const float* f1b = f1 + (size_t)b * N1 * D1;

    for (int q = 0; q < 4; ++q) {
        const int j = qbase + q;
        const float* qp = xyz2 + ((size_t)b * NP + j) * 3;
        const float qx = qp[0], qy = qp[1], qz = qp[2];

        float d0 = 3.4e38f, d1 = 3.4e38f, d2 = 3.4e38f;
        int   i0 = 0x7fffffff, i1 = 0x7fffffff, i2 = 0x7fffffff;
        for (int i = lane; i < N1; i += 32) {
            const float dx = qx - sx[3*i];
            const float dy = qy - sx[3*i+1];
            const float dz = qz - sx[3*i+2];
            const float d  = fmaf(dx, dx, fmaf(dy, dy, dz * dz));
            if (d < d2) {
                if (d < d1) {
                    d2 = d1; i2 = i1;
                    if (d < d0) { d1 = d0; i1 = i0; d0 = d; i0 = i; }
                    else        { d1 = d;  i1 = i; }
                } else { d2 = d; i2 = i; }
            }
        }
        for (int off = 16; off; off >>= 1) {
            float e0 = __shfl_xor_sync(0xffffffffu, d0, off);
            float e1 = __shfl_xor_sync(0xffffffffu, d1, off);
            float e2 = __shfl_xor_sync(0xffffffffu, d2, off);
            int   j0 = __shfl_xor_sync(0xffffffffu, i0, off);
            int   j1 = __shfl_xor_sync(0xffffffffu, i1, off);
            int   j2 = __shfl_xor_sync(0xffffffffu, i2, off);
            float r0, r1, r2; int s0, s1, s2;
            #pragma unroll
            for (int t = 0; t < 3; ++t) {
                const bool takeA = (d0 < e0) || (d0 == e0 && i0 < j0);
                float rv; int ri;
                if (takeA) { rv = d0; ri = i0; d0 = d1; i0 = i1; d1 = d2; i1 = i2; d2 = 3.4e38f; i2 = 0x7fffffff; }
                else       { rv = e0; ri = j0; e0 = e1; j0 = j1; e1 = e2; j1 = j2; e2 = 3.4e38f; j2 = 0x7fffffff; }
                if (t == 0) { r0 = rv; s0 = ri; }
                else if (t == 1) { r1 = rv; s1 = ri; }
                else { r2 = rv; s2 = ri; }
            }
            d0 = r0; d1 = r1; d2 = r2; i0 = s0; i1 = s1; i2 = s2;
        }

        float w0 = 1.0f / (d0 + F32_EPS);
        float w1 = 1.0f / (d1 + F32_EPS);
        float w2 = 1.0f / (d2 + F32_EPS);
        const float inv_sum = 1.0f / (w0 + w1 + w2);
        w0 *= inv_sum; w1 *= inv_sum; w2 *= inv_sum;

        const float4* r0p = (const float4*)(f1b + (size_t)i0 * D1);
        const float4* r1p = (const float4*)(f1b + (size_t)i1 * D1);
        const float4* r2p = (const float4*)(f1b + (size_t)i2 * D1);
        float* xo = g_x + ((size_t)b * NP + j) * DIN;
        for (int c = lane; c < D1 / 4; c += 32) {
            const float4 a = r0p[c], bb = r1p[c], cc = r2p[c];
            float4 o;
            o.x = w0*a.x + w1*bb.x + w2*cc.x;
            o.y = w0*a.y + w1*bb.y + w2*cc.y;
            o.z = w0*a.z + w1*bb.z + w2*cc.z;
            o.w = w0*a.w + w1*bb.w + w2*cc.w;
            ((float4*)xo)[c] = o;
        }
        const float4* ff2 = (const float4*)(f2 + ((size_t)b * NP + j) * D2);
        float4* xo2 = (float4*)(xo + D1);
        for (int c = lane; c < D2 / 4; c += 32) xo2[c] = ff2[c];
    }
}

// ---------------------------------------------------------------------------
// bf16 split-precision tensor-core GEMM.
// out[m][n] = sum_k A[m][k] * W[n][k] + bias[n]
// A is split elementwise as A = Ah + Al (bf16 each); W likewise. Accumulate
// Ah*Wh + Ah*Wl + Al*Wh in fp32 via mma.sync.m16n8k16 — the dropped Al*Wl term
// is ~2^-18 relative.
// BM=128, BN=64, BK=32, 256 threads = 8 warps (4 along M, 2 along N),
// warp tile 32x32. LAYER==1 fuses relu(a*x+s) (layer-1 BN) into the A load.
// Epilogue: bias add, store fp32, per-channel sum/sumsq -> g_stats.

__device__ __forceinline__ void mma_bf16(float* d, const unsigned* a, const unsigned* b) {
    asm volatile(
        "mma.sync.aligned.m16n8k16.row.col.f32.bf16.bf16.f32 "
        "{%0,%1,%2,%3}, {%4,%5,%6,%7}, {%8,%9}, {%0,%1,%2,%3};\n"
        : "+f"(d[0]), "+f"(d[1]), "+f"(d[2]), "+f"(d[3])
        : "r"(a[0]), "r"(a[1]), "r"(a[2]), "r"(a[3]), "r"(b[0]), "r"(b[1]));
}

__device__ __forceinline__ void split_bf16(float x, __nv_bfloat16& h, __nv_bfloat16& l) {
    h = __float2bfloat16_rn(x);
    l = __float2bfloat16_rn(x - __bfloat162float(h));
}

#define BK 32
#define ASTRIDE (BK + 2)   // 34 bf16 per row (row stride 68B: conflict-light)

template<int K, int LAYER>
__global__ __launch_bounds__(256) void gemm_tc_kernel(
    const float* __restrict__ W, const float* __restrict__ bias,
    float* __restrict__ out_ext)
{
    __shared__ __nv_bfloat16 AsH[128][ASTRIDE];
    __shared__ __nv_bfloat16 AsL[128][ASTRIDE];
    __shared__ __nv_bfloat16 BsH[64][ASTRIDE];
    __shared__ __nv_bfloat16 BsL[64][ASTRIDE];
    __shared__ float csum[64], csq[64];

    const float* A    = (LAYER == 0) ? g_x : g_y;
    float*       outp = (LAYER == 0) ? g_y : out_ext;
    const int SOFF = LAYER * 2 * HID;

    const int tid  = threadIdx.x;
    const int warp = tid >> 5, lane = tid & 31;
    const int wm = warp & 3, wn = warp >> 2;           // 4 M-warps x 2 N-warps
    const int g = lane >> 2, t = lane & 3;
    const int n0 = blockIdx.x * 64;                    // n-major grid for L2 reuse of A
    const int m0 = blockIdx.y * 128;

    if (tid < 64) { csum[tid] = 0.0f; csq[tid] = 0.0f; }

    float acc[2][4][4];
    #pragma unroll
    for (int i = 0; i < 2; ++i)
        #pragma unroll
        for (int j = 0; j < 4; ++j)
            #pragma unroll
            for (int v = 0; v < 4; ++v) acc[i][j][v] = 0.0f;

    // loader mapping
    const int arow = tid >> 1, aseg = (tid & 1) * 16;  // A: 2 threads/row, 16 k each
    const int brow = tid >> 2, bseg = (tid & 3) * 8;   // B: 4 threads/row, 8 k each

    for (int k0 = 0; k0 < K; k0 += BK) {
        __syncthreads();   // protect previous tile's reads
        // --- A tile: 128 x 32 fp32 -> split bf16 ---
        {
            const float* ap = A + (size_t)(m0 + arow) * K + k0 + aseg;
            #pragma unroll
            for (int r = 0; r < 4; ++r) {
                float4 v = *(const float4*)(ap + r * 4);
                if (LAYER == 1) {
                    const int kc = k0 + aseg + r * 4;
                    const float4 aa = *(const float4*)&g_bn[kc];
                    const float4 ss = *(const float4*)&g_bn[HID + kc];
                    v.x = fmaxf(fmaf(v.x, aa.x, ss.x), 0.0f);
                    v.y = fmaxf(fmaf(v.y, aa.y, ss.y), 0.0f);
                    v.z = fmaxf(fmaf(v.z, aa.z, ss.z), 0.0f);
                    v.w = fmaxf(fmaf(v.w, aa.w, ss.w), 0.0f);
                }
                __nv_bfloat16 h0, l0, h1, l1, h2, l2, h3, l3;
                split_bf16(v.x, h0, l0); split_bf16(v.y, h1, l1);
                split_bf16(v.z, h2, l2); split_bf16(v.w, h3, l3);
                const int kc = aseg + r * 4;
                AsH[arow][kc] = h0; AsH[arow][kc+1] = h1; AsH[arow][kc+2] = h2; AsH[arow][kc+3] = h3;
                AsL[arow][kc] = l0; AsL[arow][kc+1] = l1; AsL[arow][kc+2] = l2; AsL[arow][kc+3] = l3;
            }
        }
        // --- B tile: 64 x 32 fp32 -> split bf16 ---
        {
            const float* bp = W + (size_t)(n0 + brow) * K + k0 + bseg;
            #pragma unroll
            for (int r = 0; r < 2; ++r) {
                const float4 v = *(const float4*)(bp + r * 4);
                __nv_bfloat16 h0, l0, h1, l1, h2, l2, h3, l3;
                split_bf16(v.x, h0, l0); split_bf16(v.y, h1, l1);
                split_bf16(v.z, h2, l2); split_bf16(v.w, h3, l3);
                const int kc = bseg + r * 4;
                BsH[brow][kc] = h0; BsH[brow][kc+1] = h1; BsH[brow][kc+2] = h2; BsH[brow][kc+3] = h3;
                BsL[brow][kc] = l0; BsL[brow][kc+1] = l1; BsL[brow][kc+2] = l2; BsL[brow][kc+3] = l3;
            }
        }
        __syncthreads();

        #pragma unroll
        for (int ks = 0; ks < 2; ++ks) {
            const int kk = ks * 16;
            unsigned ah[2][4], al[2][4], bh[4][2], bl[4][2];
            #pragma unroll
            for (int i = 0; i < 2; ++i) {
                const int r = wm * 32 + i * 16;
                ah[i][0] = *(const unsigned*)&AsH[r + g    ][kk + 2*t    ];
                ah[i][1] = *(const unsigned*)&AsH[r + g + 8][kk + 2*t    ];
                ah[i][2] = *(const unsigned*)&AsH[r + g    ][kk + 2*t + 8];
                ah[i][3] = *(const unsigned*)&AsH[r + g + 8][kk + 2*t + 8];
                al[i][0] = *(const unsigned*)&AsL[r + g    ][kk + 2*t    ];
                al[i][1] = *(const unsigned*)&AsL[r + g + 8][kk + 2*t    ];
                al[i][2] = *(const unsigned*)&AsL[r + g    ][kk + 2*t + 8];
                al[i][3] = *(const unsigned*)&AsL[r + g + 8][kk + 2*t + 8];
            }
            #pragma unroll
            for (int j = 0; j < 4; ++j) {
                const int n = wn * 32 + j * 8 + g;
                bh[j][0] = *(const unsigned*)&BsH[n][kk + 2*t    ];
                bh[j][1] = *(const unsigned*)&BsH[n][kk + 2*t + 8];
                bl[j][0] = *(const unsigned*)&BsL[n][kk + 2*t    ];
                bl[j][1] = *(const unsigned*)&BsL[n][kk + 2*t + 8];
            }
            #pragma unroll
            for (int i = 0; i < 2; ++i)
                #pragma unroll
                for (int j = 0; j < 4; ++j) {
                    mma_bf16(acc[i][j], ah[i], bh[j]);
                    mma_bf16(acc[i][j], ah[i], bl[j]);
                    mma_bf16(acc[i][j], al[i], bh[j]);
                }
        }
    }

    // --- Epilogue: bias, store fp32, per-channel stats ---
    float ps[4][2], pq[4][2];
    #pragma unroll
    for (int j = 0; j < 4; ++j) { ps[j][0]=ps[j][1]=pq[j][0]=pq[j][1]=0.0f; }

    #pragma unroll
    for (int j = 0; j < 4; ++j) {
        const int col = n0 + wn * 32 + j * 8 + 2 * t;
        const float b0 = __ldg(bias + col), b1 = __ldg(bias + col + 1);
        #pragma unroll
        for (int i = 0; i < 2; ++i) {
            const int row = m0 + wm * 32 + i * 16 + g;
            float v0 = acc[i][j][0] + b0;
            float v1 = acc[i][j][1] + b1;
            float v2 = acc[i][j][2] + b0;
            float v3 = acc[i][j][3] + b1;
            *(float2*)(outp + (size_t)row * HID + col)       = make_float2(v0, v1);
            *(float2*)(outp + (size_t)(row + 8) * HID + col) = make_float2(v2, v3);
            ps[j][0] += v0 + v2;  pq[j][0] += v0*v0 + v2*v2;
            ps[j][1] += v1 + v3;  pq[j][1] += v1*v1 + v3*v3;
        }
    }
    __syncthreads();   // csum zeroed at start; all threads past init
    #pragma unroll
    for (int j = 0; j < 4; ++j) {
        const int l = wn * 32 + j * 8 + 2 * t;
        atomicAdd(&csum[l],     ps[j][0]);
        atomicAdd(&csum[l + 1], ps[j][1]);
        atomicAdd(&csq[l],      pq[j][0]);
        atomicAdd(&csq[l + 1],  pq[j][1]);
    }
    __syncthreads();
    if (tid < 64) {
        atomicAdd(&g_stats[SOFF + n0 + tid],       csum[tid]);
        atomicAdd(&g_stats[SOFF + HID + n0 + tid], csq[tid]);
    }
}

// ---------------------------------------------------------------------------
__global__ void bn_finalize_kernel(const float* __restrict__ g,
                                   const float* __restrict__ beta, int layer)
{
    const int c = threadIdx.x;
    const float invM = 1.0f / (float)MTOT;
    const float sum = g_stats[layer * 2 * HID + c];
    const float sq  = g_stats[layer * 2 * HID + HID + c];
    const float mu  = sum * invM;
    const float var = sq * invM - mu * mu;
    const float a   = rsqrtf(var + BN_EPS) * g[c];
    g_bn[layer * 2 * HID + c]       = a;
    g_bn[layer * 2 * HID + HID + c] = beta[c] - mu * a;
}

// ---------------------------------------------------------------------------
__global__ __launch_bounds__(256) void final_norm_kernel(float* __restrict__ out)
{
    const int i = blockIdx.x * 256 + threadIdx.x;   // float4 index
    float4 v = ((float4*)out)[i];
    const int c = (i * 4) & (HID - 1);
    const float4 a = *(const float4*)&g_bn[2 * HID + c];
    const float4 s = *(const float4*)&g_bn[3 * HID + c];
    v.x = fmaxf(fmaf(v.x, a.x, s.x), 0.0f);
    v.y = fmaxf(fmaf(v.y, a.y, s.y), 0.0f);
    v.z = fmaxf(fmaf(v.z, a.z, s.z), 0.0f);
    v.w = fmaxf(fmaf(v.w, a.w, s.w), 0.0f);
    ((float4*)out)[i] = v;
}

// ---------------------------------------------------------------------------
extern "C" void kernel_launch(void* const* d_in, const int* in_sizes, int n_in,
                              void* d_out, int out_size)
{
    const float* xyz1  = (const float*)d_in[0];
    const float* xyz2  = (const float*)d_in[1];
    const float* f1    = (const float*)d_in[2];
    const float* f2    = (const float*)d_in[3];
    const float* W1    = (const float*)d_in[4];
    const float* b1    = (const float*)d_in[5];
    const float* g1    = (const float*)d_in[6];
    const float* beta1 = (const float*)d_in[7];
    const float* W2    = (const float*)d_in[8];
    const float* b2    = (const float*)d_in[9];
    const float* g2    = (const float*)d_in[10];
    const float* beta2 = (const float*)d_in[11];
    float* out = (float*)d_out;

    zero_stats_kernel<<<1, 1024>>>();
    interp_kernel<<<dim3(NP / 32, BATCH), 256>>>(xyz1, xyz2, f1, f2);
    // n-major grid: adjacent CTAs share the same A m-tile -> A stays in L2.
    gemm_tc_kernel<DIN, 0><<<dim3(HID / 64, MTOT / 128), 256>>>(W1, b1, nullptr);
    bn_finalize_kernel<<<1, HID>>>(g1, beta1, 0);
    gemm_tc_kernel<HID, 1><<<dim3(HID / 64, MTOT / 128), 256>>>(W2, b2, out);
    bn_finalize_kernel<<<1, HID>>>(g2, beta2, 1);
    final_norm_kernel<<<(MTOT * HID / 4) / 256, 256>>>(out);
}

// round 8
// speedup vs baseline: 1.4705x; 1.2709x over previous
#include <cuda_runtime.h>
#include <cuda_bf16.h>
#include <cstdint>

// Problem constants (fixed shapes per reference)
#define BATCH 16
#define N1    1024
#define NP    4096
#define D1    256
#define D2    128
#define DIN   384          // D1 + D2
#define HID   256
#define MTOT  (BATCH * NP) // 65536
#define F32_EPS 1.1920929e-07f
#define BN_EPS  1e-5f

// Scratch (static device globals: allocation-free)
__device__ __nv_bfloat16 g_xh[MTOT * DIN];   // concat input, hi bf16
__device__ __nv_bfloat16 g_xl[MTOT * DIN];   // concat input, lo bf16
__device__ float         g_y [MTOT * HID];   // layer-1 pre-BN output (fp32)
__device__ __nv_bfloat16 g_yh[MTOT * HID];   // bn(relu(y)) hi
__device__ __nv_bfloat16 g_yl[MTOT * HID];   // bn(relu(y)) lo
__device__ __nv_bfloat16 g_w1h[HID * DIN], g_w1l[HID * DIN];
__device__ __nv_bfloat16 g_w2h[HID * HID], g_w2l[HID * HID];
__device__ float g_stats[4 * HID];   // [sum1, sumsq1, sum2, sumsq2]
__device__ float g_bn[4 * HID];      // [a1, s1, a2, s2]  (y*a + s form)

// ---------------------------------------------------------------------------
// helpers
// ---------------------------------------------------------------------------
__device__ __forceinline__ uint32_t smem_u32(const void* p) {
    uint32_t a;
    asm("{ .reg .u64 t; cvta.to.shared.u64 t, %1; cvt.u32.u64 %0, t; }" : "=r"(a) : "l"(p));
    return a;
}
__device__ __forceinline__ uint32_t sw128(uint32_t off) {
    return off ^ ((off >> 3) & 0x70);
}
// Split two floats into packed hi/lo bf16x2 words.
__device__ __forceinline__ uint32_t pack2(float x, float y, uint32_t& lo) {
    __nv_bfloat16 hx = __float2bfloat16_rn(x);
    __nv_bfloat16 hy = __float2bfloat16_rn(y);
    __nv_bfloat16 lx = __float2bfloat16_rn(x - __bfloat162float(hx));
    __nv_bfloat16 ly = __float2bfloat16_rn(y - __bfloat162float(hy));
    lo = ((uint32_t)__bfloat16_as_ushort(ly) << 16) | __bfloat16_as_ushort(lx);
    return ((uint32_t)__bfloat16_as_ushort(hy) << 16) | __bfloat16_as_ushort(hx);
}
__device__ __forceinline__ void cp16(uint32_t s, const void* g) {
    asm volatile("cp.async.cg.shared.global [%0], [%1], 16;" :: "r"(s), "l"(g));
}
__device__ __forceinline__ void ldsm4(unsigned* r, uint32_t addr) {
    asm volatile("ldmatrix.sync.aligned.m8n8.x4.shared.b16 {%0,%1,%2,%3}, [%4];"
                 : "=r"(r[0]), "=r"(r[1]), "=r"(r[2]), "=r"(r[3]) : "r"(addr));
}
__device__ __forceinline__ void mma_b(float* d, const unsigned* a, unsigned b0, unsigned b1) {
    asm volatile(
        "mma.sync.aligned.m16n8k16.row.col.f32.bf16.bf16.f32 "
        "{%0,%1,%2,%3}, {%4,%5,%6,%7}, {%8,%9}, {%0,%1,%2,%3};\n"
        : "+f"(d[0]), "+f"(d[1]), "+f"(d[2]), "+f"(d[3])
        : "r"(a[0]), "r"(a[1]), "r"(a[2]), "r"(a[3]), "r"(b0), "r"(b1));
}

// ---------------------------------------------------------------------------
// 3-NN inverse-distance interpolation + concat; writes split bf16 directly.
// Block (0,0) also zeroes g_stats.
__global__ __launch_bounds__(256) void interp_kernel(
    const float* __restrict__ xyz1, const float* __restrict__ xyz2,
    const float* __restrict__ f1,   const float* __restrict__ f2)
{
    __shared__ float sx[N1 * 3];
    const int b = blockIdx.y;
    if (b == 0 && blockIdx.x == 0)
        for (int i = threadIdx.x; i < 4 * HID; i += 256) g_stats[i] = 0.0f;
    const float* x1b = xyz1 + (size_t)b * N1 * 3;
    for (int i = threadIdx.x; i < N1 * 3; i += blockDim.x) sx[i] = x1b[i];
    __syncthreads();

    const int warp = threadIdx.x >> 5, lane = threadIdx.x & 31;
    const int qbase = blockIdx.x * 32 + warp * 4;
    const float* f1b = f1 + (size_t)b * N1 * D1;

    for (int q = 0; q < 4; ++q) {
        const int j = qbase + q;
        const float* qp = xyz2 + ((size_t)b * NP + j) * 3;
        const float qx = qp[0], qy = qp[1], qz = qp[2];

        float d0 = 3.4e38f, d1 = 3.4e38f, d2 = 3.4e38f;
        int   i0 = 0x7fffffff, i1 = 0x7fffffff, i2 = 0x7fffffff;
        for (int i = lane; i < N1; i += 32) {
            const float dx = qx - sx[3*i];
            const float dy = qy - sx[3*i+1];
            const float dz = qz - sx[3*i+2];
            const float d  = fmaf(dx, dx, fmaf(dy, dy, dz * dz));
            if (d < d2) {
                if (d < d1) {
                    d2 = d1; i2 = i1;
                    if (d < d0) { d1 = d0; i1 = i0; d0 = d; i0 = i; }
                    else        { d1 = d;  i1 = i; }
                } else { d2 = d; i2 = i; }
            }
        }
        for (int off = 16; off; off >>= 1) {
            float e0 = __shfl_xor_sync(0xffffffffu, d0, off);
            float e1 = __shfl_xor_sync(0xffffffffu, d1, off);
            float e2 = __shfl_xor_sync(0xffffffffu, d2, off);
            int   j0 = __shfl_xor_sync(0xffffffffu, i0, off);
            int   j1 = __shfl_xor_sync(0xffffffffu, i1, off);
            int   j2 = __shfl_xor_sync(0xffffffffu, i2, off);
            float r0, r1, r2; int s0, s1, s2;
            #pragma unroll
            for (int t = 0; t < 3; ++t) {
                const bool takeA = (d0 < e0) || (d0 == e0 && i0 < j0);
                float rv; int ri;
                if (takeA) { rv = d0; ri = i0; d0 = d1; i0 = i1; d1 = d2; i1 = i2; d2 = 3.4e38f; i2 = 0x7fffffff; }
                else       { rv = e0; ri = j0; e0 = e1; j0 = j1; e1 = e2; j1 = j2; e2 = 3.4e38f; j2 = 0x7fffffff; }
                if (t == 0) { r0 = rv; s0 = ri; }
                else if (t == 1) { r1 = rv; s1 = ri; }
                else { r2 = rv; s2 = ri; }
            }
            d0 = r0; d1 = r1; d2 = r2; i0 = s0; i1 = s1; i2 = s2;
        }

        float w0 = 1.0f / (d0 + F32_EPS);
        float w1 = 1.0f / (d1 + F32_EPS);
        float w2 = 1.0f / (d2 + F32_EPS);
        const float inv_sum = 1.0f / (w0 + w1 + w2);
        w0 *= inv_sum; w1 *= inv_sum; w2 *= inv_sum;

        const float4* r0p = (const float4*)(f1b + (size_t)i0 * D1);
        const float4* r1p = (const float4*)(f1b + (size_t)i1 * D1);
        const float4* r2p = (const float4*)(f1b + (size_t)i2 * D1);
        const size_t rowoff = ((size_t)b * NP + j) * DIN;
        uint2* xh = (uint2*)(g_xh + rowoff);
        uint2* xl = (uint2*)(g_xl + rowoff);
        for (int c = lane; c < D1 / 4; c += 32) {
            const float4 a = r0p[c], bb = r1p[c], cc = r2p[c];
            float4 o;
            o.x = w0*a.x + w1*bb.x + w2*cc.x;
            o.y = w0*a.y + w1*bb.y + w2*cc.y;
            o.z = w0*a.z + w1*bb.z + w2*cc.z;
            o.w = w0*a.w + w1*bb.w + w2*cc.w;
            uint2 hi, lo;
            hi.x = pack2(o.x, o.y, lo.x);
            hi.y = pack2(o.z, o.w, lo.y);
            xh[c] = hi; xl[c] = lo;
        }
        const float4* ff2 = (const float4*)(f2 + ((size_t)b * NP + j) * D2);
        uint2* xh2 = (uint2*)(g_xh + rowoff + D1);
        uint2* xl2 = (uint2*)(g_xl + rowoff + D1);
        for (int c = lane; c < D2 / 4; c += 32) {
            const float4 v = ff2[c];
            uint2 hi, lo;
            hi.x = pack2(v.x, v.y, lo.x);
            hi.y = pack2(v.z, v.w, lo.y);
            xh2[c] = hi; xl2[c] = lo;
        }
    }
}

// ---------------------------------------------------------------------------
// Split W1 and W2 into bf16 hi/lo (one launch).
__global__ __launch_bounds__(256) void conv_w_kernel(
    const float* __restrict__ W1, const float* __restrict__ W2)
{
    const int i = blockIdx.x * 256 + threadIdx.x;   // float4 index
    constexpr int N1F4 = HID * DIN / 4;             // 24576
    constexpr int N2F4 = HID * HID / 4;             // 16384
    if (i >= N1F4 + N2F4) return;
    float4 v; uint2* ph; uint2* pl;
    if (i < N1F4) {
        v = ((const float4*)W1)[i];
        ph = (uint2*)g_w1h + i; pl = (uint2*)g_w1l + i;
    } else {
        v = ((const float4*)W2)[i - N1F4];
        ph = (uint2*)g_w2h + (i - N1F4); pl = (uint2*)g_w2l + (i - N1F4);
    }
    uint2 hi, lo;
    hi.x = pack2(v.x, v.y, lo.x);
    hi.y = pack2(v.z, v.w, lo.y);
    *ph = hi; *pl = lo;
}

// ---------------------------------------------------------------------------
// bf16 split-precision mma.sync GEMM with ldmatrix + cp.async double buffer.
// out[m][n] = sum_k A[m][k] * W[n][k] + bias[n]
// BM=128, BN=64, BK=64, 8 warps (4 m x 2 n), warp tile 32x32.
// 3 passes: Ah*Wh + Ah*Wl + Al*Wh (fp32 accum); dropped Al*Wl ~2^-18.
// Epilogue: bias add, fp32 store, per-channel sum/sumsq -> g_stats.
//
// SMEM per stage (49152 B): Ah[128x128B] @0, Al @16384, Bh[64x128B] @32768,
// Bl @40960. Two stages = 98304 B dynamic.

#define STG 49152u

template<int K, int LAYER>
__global__ __launch_bounds__(256, 2) void gemm_mma_kernel(
    const float* __restrict__ bias, float* __restrict__ out_ext)
{
    extern __shared__ char smem[];
    __shared__ float csum[64], csq[64];
    const uint32_t sb = smem_u32(smem);
    const int tid = threadIdx.x, lane = tid & 31, warp = tid >> 5;
    const int wm = warp & 3, wn = warp >> 2;
    const int n0 = blockIdx.x * 64;     // n-major grid: A m-tile reused via L2
    const int m0 = blockIdx.y * 128;

    const __nv_bfloat16* Ah = (LAYER == 0) ? g_xh  : g_yh;
    const __nv_bfloat16* Al = (LAYER == 0) ? g_xl  : g_yl;
    const __nv_bfloat16* Bh = (LAYER == 0) ? g_w1h : g_w2h;
    const __nv_bfloat16* Bl = (LAYER == 0) ? g_w1l : g_w2l;
    float* outp = (LAYER == 0) ? g_y : out_ext;
    constexpr int NKT = K / 64;

    if (tid < 64) { csum[tid] = 0.0f; csq[tid] = 0.0f; }

    float acc[2][4][4];
    #pragma unroll
    for (int i = 0; i < 2; ++i)
        #pragma unroll
        for (int j = 0; j < 4; ++j)
            #pragma unroll
            for (int v = 0; v < 4; ++v) acc[i][j][v] = 0.0f;

    // stage loader: 256 threads, 16B chunks, SW128 swizzled
    auto load_stage = [&](int buf, int k0) {
        const uint32_t st = sb + buf * STG;
        #pragma unroll
        for (int c = 0; c < 4; ++c) {                     // A: 128 rows x 128B
            const int idx = tid + c * 256;
            const int row = idx >> 3, col = idx & 7;
            const uint32_t so = sw128((uint32_t)(row * 128 + col * 16));
            const size_t go = (size_t)(m0 + row) * K + k0 + col * 8;
            cp16(st + so,          Ah + go);
            cp16(st + 16384u + so, Al + go);
        }
        #pragma unroll
        for (int c = 0; c < 2; ++c) {                     // B: 64 rows x 128B
            const int idx = tid + c * 256;
            const int row = idx >> 3, col = idx & 7;
            const uint32_t so = sw128((uint32_t)(row * 128 + col * 16));
            const size_t go = (size_t)(n0 + row) * K + k0 + col * 8;
            cp16(st + 32768u + so, Bh + go);
            cp16(st + 40960u + so, Bl + go);
        }
        asm volatile("cp.async.commit_group;" ::: "memory");
    };

    load_stage(0, 0);
    for (int kt = 0; kt < NKT; ++kt) {
        if (kt + 1 < NKT) {
            load_stage((kt + 1) & 1, (kt + 1) * 64);
            asm volatile("cp.async.wait_group 1;" ::: "memory");
        } else {
            asm volatile("cp.async.wait_group 0;" ::: "memory");
        }
        __syncthreads();

        const uint32_t st = sb + (kt & 1) * STG;
        // ldmatrix lane addressing: which = lane>>3 selects (row+8?, k+8?)
        const int which = lane >> 3, r8 = lane & 7;
        const int rowadd = r8 + (which & 1) * 8;
        const int kadd = (which >> 1) * 16;               // bytes

        #pragma unroll
        for (int ks = 0; ks < 4; ++ks) {
            const int kb = ks * 32 + kadd;                // byte offset of k16 step
            unsigned ah[2][4], al[2][4], bh[2][4], bl[2][4];
            #pragma unroll
            for (int i = 0; i < 2; ++i) {
                const uint32_t off = sw128((uint32_t)((wm * 32 + i * 16 + rowadd) * 128 + kb));
                ldsm4(ah[i], st + off);
                ldsm4(al[i], st + 16384u + off);
            }
            #pragma unroll
            for (int b = 0; b < 2; ++b) {
                const uint32_t off = sw128((uint32_t)((wn * 32 + b * 16 + rowadd) * 128 + kb));
                ldsm4(bh[b], st + 32768u + off);
                ldsm4(bl[b], st + 40960u + off);
            }
            #pragma unroll
            for (int i = 0; i < 2; ++i)
                #pragma unroll
                for (int j = 0; j < 4; ++j) {
                    const int blk = j >> 1, s = j & 1;
                    mma_b(acc[i][j], ah[i], bh[blk][s], bh[blk][s + 2]);
                    mma_b(acc[i][j], ah[i], bl[blk][s], bl[blk][s + 2]);
                    mma_b(acc[i][j], al[i], bh[blk][s], bh[blk][s + 2]);
                }
        }
        __syncthreads();
    }

    // --- Epilogue: bias, store fp32, per-channel stats ---
    const int g = lane >> 2, t = lane & 3;
    float ps[4][2], pq[4][2];
    #pragma unroll
    for (int j = 0; j < 4; ++j) { ps[j][0]=ps[j][1]=pq[j][0]=pq[j][1]=0.0f; }

    #pragma unroll
    for (int j = 0; j < 4; ++j) {
        const int col = n0 + wn * 32 + j * 8 + 2 * t;
        const float b0 = __ldg(bias + col), b1 = __ldg(bias + col + 1);
        #pragma unroll
        for (int i = 0; i < 2; ++i) {
            const int row = m0 + wm * 32 + i * 16 + g;
            float v0 = acc[i][j][0] + b0;
            float v1 = acc[i][j][1] + b1;
            float v2 = acc[i][j][2] + b0;
            float v3 = acc[i][j][3] + b1;
            *(float2*)(outp + (size_t)row * HID + col)       = make_float2(v0, v1);
            *(float2*)(outp + (size_t)(row + 8) * HID + col) = make_float2(v2, v3);
            ps[j][0] += v0 + v2;  pq[j][0] += v0*v0 + v2*v2;
            ps[j][1] += v1 + v3;  pq[j][1] += v1*v1 + v3*v3;
        }
    }
    #pragma unroll
    for (int j = 0; j < 4; ++j) {
        const int l = wn * 32 + j * 8 + 2 * t;
        atomicAdd(&csum[l],     ps[j][0]);
        atomicAdd(&csum[l + 1], ps[j][1]);
        atomicAdd(&csq[l],      pq[j][0]);
        atomicAdd(&csq[l + 1],  pq[j][1]);
    }
    __syncthreads();
    if (tid < 64) {
        const int SOFF = LAYER * 2 * HID;
        atomicAdd(&g_stats[SOFF + n0 + tid],       csum[tid]);
        atomicAdd(&g_stats[SOFF + HID + n0 + tid], csq[tid]);
    }
}

// ---------------------------------------------------------------------------
__global__ void bn_finalize_kernel(const float* __restrict__ g,
                                   const float* __restrict__ beta, int layer)
{
    const int c = threadIdx.x;
    const float invM = 1.0f / (float)MTOT;
    const float sum = g_stats[layer * 2 * HID + c];
    const float sq  = g_stats[layer * 2 * HID + HID + c];
    const float mu  = sum * invM;
    const float var = sq * invM - mu * mu;
    const float a   = rsqrtf(var + BN_EPS) * g[c];
    g_bn[layer * 2 * HID + c]       = a;
    g_bn[layer * 2 * HID + HID + c] = beta[c] - mu * a;
}

// ---------------------------------------------------------------------------
// Apply layer-1 BN+ReLU to g_y and emit split bf16 for GEMM2.
__global__ __launch_bounds__(256) void conv_y_kernel()
{
    const int i = blockIdx.x * 256 + threadIdx.x;   // float4 index
    float4 v = ((const float4*)g_y)[i];
    const int c = (i * 4) & (HID - 1);
    const float4 a = *(const float4*)&g_bn[c];
    const float4 s = *(const float4*)&g_bn[HID + c];
    v.x = fmaxf(fmaf(v.x, a.x, s.x), 0.0f);
    v.y = fmaxf(fmaf(v.y, a.y, s.y), 0.0f);
    v.z = fmaxf(fmaf(v.z, a.z, s.z), 0.0f);
    v.w = fmaxf(fmaf(v.w, a.w, s.w), 0.0f);
    uint2 hi, lo;
    hi.x = pack2(v.x, v.y, lo.x);
    hi.y = pack2(v.z, v.w, lo.y);
    ((uint2*)g_yh)[i] = hi;
    ((uint2*)g_yl)[i] = lo;
}

// ---------------------------------------------------------------------------
__global__ __launch_bounds__(256) void final_norm_kernel(float* __restrict__ out)
{
    const int i = blockIdx.x * 256 + threadIdx.x;   // float4 index
    float4 v = ((float4*)out)[i];
    const int c = (i * 4) & (HID - 1);
    const float4 a = *(const float4*)&g_bn[2 * HID + c];
    const float4 s = *(const float4*)&g_bn[3 * HID + c];
    v.x = fmaxf(fmaf(v.x, a.x, s.x), 0.0f);
    v.y = fmaxf(fmaf(v.y, a.y, s.y), 0.0f);
    v.z = fmaxf(fmaf(v.z, a.z, s.z), 0.0f);
    v.w = fmaxf(fmaf(v.w, a.w, s.w), 0.0f);
    ((float4*)out)[i] = v;
}

// ---------------------------------------------------------------------------
extern "C" void kernel_launch(void* const* d_in, const int* in_sizes, int n_in,
                              void* d_out, int out_size)
{
    const float* xyz1  = (const float*)d_in[0];
    const float* xyz2  = (const float*)d_in[1];
    const float* f1    = (const float*)d_in[2];
    const float* f2    = (const float*)d_in[3];
    const float* W1    = (const float*)d_in[4];
    const float* b1    = (const float*)d_in[5];
    const float* g1    = (const float*)d_in[6];
    const float* beta1 = (const float*)d_in[7];
    const float* W2    = (const float*)d_in[8];
    const float* b2    = (const float*)d_in[9];
    const float* g2    = (const float*)d_in[10];
    const float* beta2 = (const float*)d_in[11];
    float* out = (float*)d_out;

    cudaFuncSetAttribute(gemm_mma_kernel<DIN, 0>,
                         cudaFuncAttributeMaxDynamicSharedMemorySize, 2 * STG);
    cudaFuncSetAttribute(gemm_mma_kernel<HID, 1>,
                         cudaFuncAttributeMaxDynamicSharedMemorySize, 2 * STG);

    interp_kernel<<<dim3(NP / 32, BATCH), 256>>>(xyz1, xyz2, f1, f2);
    conv_w_kernel<<<(HID * DIN / 4 + HID * HID / 4 + 255) / 256, 256>>>(W1, W2);

    gemm_mma_kernel<DIN, 0><<<dim3(HID / 64, MTOT / 128), 256, 2 * STG>>>(b1, nullptr);
    bn_finalize_kernel<<<1, HID>>>(g1, beta1, 0);
    conv_y_kernel<<<MTOT * HID / 4 / 256, 256>>>();

    gemm_mma_kernel<HID, 1><<<dim3(HID / 64, MTOT / 128), 256, 2 * STG>>>(b2, out);
    bn_finalize_kernel<<<1, HID>>>(g2, beta2, 1);
    final_norm_kernel<<<MTOT * HID / 4 / 256, 256>>>(out);
}